// round 8
// baseline (speedup 1.0000x reference)
#include <cuda_runtime.h>
#include <math.h>
#include <stdint.h>

#define NMAX 50000
#define EMAX 800000
#define CDIM 128
#define PADA 136   // A-chunk col pitch (floats)

// ---------------- device scratch ----------------
__device__ int   g_is64;
__device__ float g_xf [(size_t)NMAX * CDIM];
__device__ float g_agg[(size_t)NMAX * CDIM];
__device__ float g_delta[(size_t)NMAX * 3];
__device__ int   g_src [EMAX];
__device__ int   g_dst [EMAX];
__device__ int   g_esrc[EMAX];
__device__ int   g_cnt [NMAX];
__device__ int   g_cur [NMAX];
__device__ int   g_off [NMAX + 1];
__device__ int   g_bsum[64];
__device__ int   g_bpre[64];

// ---------------- f32x2 helpers ----------------
__device__ __forceinline__ unsigned long long splat2(float a) {
    unsigned long long r;
    asm("mov.b64 %0, {%1, %1};" : "=l"(r) : "f"(a));
    return r;
}
__device__ __forceinline__ void fma2(unsigned long long& d, unsigned long long a, unsigned long long b) {
    asm("fma.rn.f32x2 %0, %1, %2, %0;" : "+l"(d) : "l"(a), "l"(b));
}
__device__ __forceinline__ float2 unpk(unsigned long long v) {
    float lo, hi;
    asm("mov.b64 {%0, %1}, %2;" : "=f"(lo), "=f"(hi) : "l"(v));
    return make_float2(lo, hi);
}
__device__ __forceinline__ float lrelu(float v) { return (v > 0.f) ? v : 0.01f * v; }

// ---------------- dtype detection ----------------
__global__ void detect_kernel(const unsigned int* __restrict__ w, int E) {
    int nz = 0;
    int lim = 2 * E;
    for (int i = threadIdx.x; i < 256; i += 32) {
        int wi = 2 * i + 1;
        if (wi < lim) nz |= (w[wi] != 0u);
    }
    nz = __any_sync(0xffffffffu, nz);
    if (threadIdx.x == 0) g_is64 = nz ? 0 : 1;
}

__global__ void zero_cnt_kernel(int n) {
    int i = blockIdx.x * blockDim.x + threadIdx.x;
    if (i < n) { g_cnt[i] = 0; g_cur[i] = 0; }
}

__global__ void convert_hist_kernel(const void* __restrict__ ei, int E) {
    int i = blockIdx.x * blockDim.x + threadIdx.x;
    if (i >= E) return;
    int s, d;
    if (g_is64) {
        const long long* p = (const long long*)ei;
        s = (int)p[i];
        d = (int)p[E + i];
    } else {
        const int* p = (const int*)ei;
        s = p[i];
        d = p[E + i];
    }
    g_src[i] = s;
    g_dst[i] = d;
    atomicAdd(&g_cnt[d], 1);
}

// ---------------- hierarchical scan ----------------
__global__ void scanA_kernel(int n) {
    __shared__ int wsum[32];
    int tid = threadIdx.x, lane = tid & 31, wid = tid >> 5;
    int i = blockIdx.x * 1024 + tid;
    int v = (i < n) ? g_cnt[i] : 0;
    int x = v;
    #pragma unroll
    for (int d = 1; d < 32; d <<= 1) {
        int t = __shfl_up_sync(0xffffffffu, x, d);
        if (lane >= d) x += t;
    }
    if (lane == 31) wsum[wid] = x;
    __syncthreads();
    if (wid == 0) {
        int s = wsum[lane];
        #pragma unroll
        for (int d = 1; d < 32; d <<= 1) {
            int t = __shfl_up_sync(0xffffffffu, s, d);
            if (lane >= d) s += t;
        }
        wsum[lane] = s;
    }
    __syncthreads();
    if (wid > 0) x += wsum[wid - 1];
    if (i < n) g_off[i + 1] = x;
    if (tid == 1023) g_bsum[blockIdx.x] = x;
}

__global__ void scanB_kernel(int nb) {
    __shared__ int ws[2];
    int t = threadIdx.x, lane = t & 31, w = t >> 5;
    int v = (t < nb) ? g_bsum[t] : 0;
    int x = v;
    #pragma unroll
    for (int d = 1; d < 32; d <<= 1) {
        int u = __shfl_up_sync(0xffffffffu, x, d);
        if (lane >= d) x += u;
    }
    if (lane == 31) ws[w] = x;
    __syncthreads();
    if (w == 1) x += ws[0];
    if (t < nb) g_bpre[t] = x - v;
}

__global__ void scanC_kernel(int n) {
    int i = blockIdx.x * 1024 + threadIdx.x;
    int add = g_bpre[blockIdx.x];
    if (i < n) g_off[i + 1] += add;
    if (i == 0) g_off[0] = 0;
}

__global__ void scatter_kernel(int E) {
    int i = blockIdx.x * blockDim.x + threadIdx.x;
    if (i >= E) return;
    int d = g_dst[i];
    int p = g_off[d] + atomicAdd(&g_cur[d], 1);
    g_esrc[p] = g_src[i];
}

// ---------------- GEMM core: 32-col chunks, double-buffered A, 4 barriers ----------------
__device__ __forceinline__ void stA(float* As, int c, int r, float4 v) {
    As[(c + 0) * PADA + r] = v.x;
    As[(c + 1) * PADA + r] = v.y;
    As[(c + 2) * PADA + r] = v.z;
    As[(c + 3) * PADA + r] = v.w;
}

__device__ __forceinline__ void compute16(
    const float* cur, const float* Bs, int kglob, unsigned long long acc[8][4],
    int koff, int tx, int ty)
{
    #pragma unroll
    for (int k = 0; k < 16; k++) {
        float4 a0 = *(float4*)&cur[(koff + k) * PADA + ty * 8];
        float4 a1 = *(float4*)&cur[(koff + k) * PADA + ty * 8 + 4];
        const float* br = &Bs[(kglob + k) * 128];
        ulonglong2 b01 = *(const ulonglong2*)&br[tx * 4];
        ulonglong2 b23 = *(const ulonglong2*)&br[64 + tx * 4];
        float av[8] = {a0.x, a0.y, a0.z, a0.w, a1.x, a1.y, a1.z, a1.w};
        #pragma unroll
        for (int i = 0; i < 8; i++) {
            unsigned long long as_ = splat2(av[i]);
            fma2(acc[i][0], as_, b01.x);
            fma2(acc[i][1], as_, b01.y);
            fma2(acc[i][2], as_, b23.x);
            fma2(acc[i][3], as_, b23.y);
        }
    }
}

// staging map: r_ = tid>>2 (0..63), c_ = (tid&3)*4 (0..12); each thread covers
// rows {r_, r_+64} x cols {c_, c_+16} of the 128x32 chunk (4 float4 loads).
__device__ __forceinline__ void gemm_core32(
    const float* __restrict__ A, int M, int row0,
    const float* Bs, float* As0, float* As1, unsigned long long acc[8][4],
    int tid, int tx, int ty)
{
    int r_ = tid >> 2;
    int c_ = (tid & 3) * 4;
    int g0 = row0 + r_;
    int g1 = row0 + 64 + r_;
    const float* A0 = &A[(size_t)g0 * 128 + c_];
    const float* A1 = &A[(size_t)g1 * 128 + c_];
    bool ok0 = g0 < M, ok1 = g1 < M;

    // stage chunk 0
    {
        float4 u0 = make_float4(0.f, 0.f, 0.f, 0.f), u1 = u0, u2 = u0, u3 = u0;
        if (ok0) { u0 = *(const float4*)A0; u2 = *(const float4*)(A0 + 16); }
        if (ok1) { u1 = *(const float4*)A1; u3 = *(const float4*)(A1 + 16); }
        stA(As0, c_,      r_,      u0);
        stA(As0, c_,      64 + r_, u1);
        stA(As0, c_ + 16, r_,      u2);
        stA(As0, c_ + 16, 64 + r_, u3);
    }
    __syncthreads();   // also covers B staging done by caller

    #pragma unroll
    for (int ch = 0; ch < 4; ch++) {
        float* cur = (ch & 1) ? As1 : As0;
        float* nxt = (ch & 1) ? As0 : As1;
        int kbase = ch * 32;
        float4 u0 = make_float4(0.f, 0.f, 0.f, 0.f), u1 = u0;
        if (ch < 3) {   // prefetch pair1 of next chunk (cols +0..3)
            int off = (ch + 1) * 32;
            if (ok0) u0 = *(const float4*)(A0 + off);
            if (ok1) u1 = *(const float4*)(A1 + off);
        }
        compute16(cur, Bs, kbase, acc, 0, tx, ty);
        if (ch < 3) {   // store pair1, prefetch pair2 (cols +16..19)
            stA(nxt, c_, r_,      u0);
            stA(nxt, c_, 64 + r_, u1);
            int off = (ch + 1) * 32 + 16;
            u0 = make_float4(0.f, 0.f, 0.f, 0.f); u1 = u0;
            if (ok0) u0 = *(const float4*)(A0 + off);
            if (ok1) u1 = *(const float4*)(A1 + off);
        }
        compute16(cur, Bs, kbase + 16, acc, 16, tx, ty);
        if (ch < 3) {
            stA(nxt, c_ + 16, r_,      u0);
            stA(nxt, c_ + 16, 64 + r_, u1);
        }
        __syncthreads();
    }
}

// ---------------- xf = x @ Wf_x + bf ----------------
__global__ __launch_bounds__(256, 2)
void gemm_bias_kernel(const float* __restrict__ A, const float* __restrict__ B,
                      const float* __restrict__ bias, float* __restrict__ O, int M) {
    extern __shared__ float sm[];
    float* Bs  = sm;                 // 16384
    float* As0 = sm + 16384;         // 32*PADA = 4352
    float* As1 = As0 + 32 * PADA;    // 4352
    int tid = threadIdx.x, tx = tid & 15, ty = tid >> 4;
    int row0 = blockIdx.x * 128;

    #pragma unroll
    for (int it = 0; it < 16; ++it) {
        int idx = (it * 256 + tid) * 4;
        *(float4*)&Bs[idx] = *(const float4*)&B[idx];
    }
    unsigned long long acc[8][4];
    #pragma unroll
    for (int i = 0; i < 8; i++)
        #pragma unroll
        for (int j = 0; j < 4; j++) acc[i][j] = 0ull;

    gemm_core32(A, M, row0, Bs, As0, As1, acc, tid, tx, ty);

    float4 bA = *(const float4*)&bias[tx * 4];
    float4 bB = *(const float4*)&bias[64 + tx * 4];
    #pragma unroll
    for (int i = 0; i < 8; i++) {
        int grow = row0 + ty * 8 + i;
        if (grow >= M) continue;
        float2 f0 = unpk(acc[i][0]), f1 = unpk(acc[i][1]);
        float2 f2 = unpk(acc[i][2]), f3 = unpk(acc[i][3]);
        *(float4*)&O[(size_t)grow * 128 + tx * 4] =
            make_float4(f0.x + bA.x, f0.y + bA.y, f1.x + bA.z, f1.y + bA.w);
        *(float4*)&O[(size_t)grow * 128 + 64 + tx * 4] =
            make_float4(f2.x + bB.x, f2.y + bB.y, f3.x + bB.z, f3.y + bB.w);
    }
}

// ---------------- delta = tanh(lrelu(x@Wh1+bh1) @ Wh2 + bh2), fused ----------------
__global__ __launch_bounds__(256, 2)
void gemm_hdelta_kernel(const float* __restrict__ A, const float* __restrict__ B,
                        const float* __restrict__ bias,
                        const float* __restrict__ Wh2, const float* __restrict__ bh2, int M) {
    extern __shared__ float sm[];
    float* Bs   = sm;                  // 16384
    float* As0  = sm + 16384;          // 4352
    float* As1  = As0 + 32 * PADA;     // 4352
    float* sW2  = As1 + 32 * PADA;     // 384
    float* sdel = sW2 + 384;           // 384
    int tid = threadIdx.x, tx = tid & 15, ty = tid >> 4;
    int row0 = blockIdx.x * 128;

    #pragma unroll
    for (int it = 0; it < 16; ++it) {
        int idx = (it * 256 + tid) * 4;
        *(float4*)&Bs[idx] = *(const float4*)&B[idx];
    }
    if (tid < 96) *(float4*)&sW2[tid * 4] = *(const float4*)&Wh2[tid * 4];

    unsigned long long acc[8][4];
    #pragma unroll
    for (int i = 0; i < 8; i++)
        #pragma unroll
        for (int j = 0; j < 4; j++) acc[i][j] = 0ull;

    gemm_core32(A, M, row0, Bs, As0, As1, acc, tid, tx, ty);

    float4 bA = *(const float4*)&bias[tx * 4];
    float4 bB = *(const float4*)&bias[64 + tx * 4];
    float bb[8] = {bA.x, bA.y, bA.z, bA.w, bB.x, bB.y, bB.z, bB.w};

    #pragma unroll
    for (int i = 0; i < 8; i++) {
        float p0 = 0.f, p1 = 0.f, p2 = 0.f;
        #pragma unroll
        for (int j = 0; j < 4; j++) {
            int c0 = (j < 2) ? (tx * 4 + j * 2) : (64 + tx * 4 + (j - 2) * 2);
            float2 f = unpk(acc[i][j]);
            f.x = lrelu(f.x + bb[j * 2 + 0]);
            f.y = lrelu(f.y + bb[j * 2 + 1]);
            p0 += f.x * sW2[c0 * 3 + 0] + f.y * sW2[(c0 + 1) * 3 + 0];
            p1 += f.x * sW2[c0 * 3 + 1] + f.y * sW2[(c0 + 1) * 3 + 1];
            p2 += f.x * sW2[c0 * 3 + 2] + f.y * sW2[(c0 + 1) * 3 + 2];
        }
        #pragma unroll
        for (int d = 1; d < 16; d <<= 1) {
            p0 += __shfl_xor_sync(0xffffffffu, p0, d);
            p1 += __shfl_xor_sync(0xffffffffu, p1, d);
            p2 += __shfl_xor_sync(0xffffffffu, p2, d);
        }
        if (tx == 0) {
            int r = ty * 8 + i;
            sdel[r * 3 + 0] = p0;
            sdel[r * 3 + 1] = p1;
            sdel[r * 3 + 2] = p2;
        }
    }
    __syncthreads();
    if (tid < 128) {
        int grow = row0 + tid;
        if (grow < M) {
            g_delta[grow * 3 + 0] = tanhf(sdel[tid * 3 + 0] + bh2[0]);
            g_delta[grow * 3 + 1] = tanhf(sdel[tid * 3 + 1] + bh2[1]);
            g_delta[grow * 3 + 2] = tanhf(sdel[tid * 3 + 2] + bh2[2]);
        }
    }
}

// ---------------- edge aggregation: warp per dst node, unroll 4 ----------------
__global__ void agg_kernel(const float* __restrict__ pos, const float* __restrict__ Wf, int N) {
    int warp = (blockIdx.x * blockDim.x + threadIdx.x) >> 5;
    int lane = threadIdx.x & 31;
    if (warp >= N) return;
    int c = lane * 4;
    float4 w0 = *(const float4*)&Wf[c];
    float4 w1 = *(const float4*)&Wf[128 + c];
    float4 w2 = *(const float4*)&Wf[256 + c];
    float bx = g_delta[warp * 3 + 0] - pos[warp * 3 + 0];
    float by = g_delta[warp * 3 + 1] - pos[warp * 3 + 1];
    float bz = g_delta[warp * 3 + 2] - pos[warp * 3 + 2];
    int p0 = g_off[warp], p1 = g_off[warp + 1];
    float4 acc = make_float4(-INFINITY, -INFINITY, -INFINITY, -INFINITY);
    int p = p0;
    for (; p + 4 <= p1; p += 4) {
        int s0 = g_esrc[p + 0];
        int s1 = g_esrc[p + 1];
        int s2 = g_esrc[p + 2];
        int s3 = g_esrc[p + 3];
        float rx0 = pos[s0 * 3 + 0] + bx, ry0 = pos[s0 * 3 + 1] + by, rz0 = pos[s0 * 3 + 2] + bz;
        float rx1 = pos[s1 * 3 + 0] + bx, ry1 = pos[s1 * 3 + 1] + by, rz1 = pos[s1 * 3 + 2] + bz;
        float rx2 = pos[s2 * 3 + 0] + bx, ry2 = pos[s2 * 3 + 1] + by, rz2 = pos[s2 * 3 + 2] + bz;
        float rx3 = pos[s3 * 3 + 0] + bx, ry3 = pos[s3 * 3 + 1] + by, rz3 = pos[s3 * 3 + 2] + bz;
        float4 v0 = *(const float4*)&g_xf[(size_t)s0 * 128 + c];
        float4 v1 = *(const float4*)&g_xf[(size_t)s1 * 128 + c];
        float4 v2 = *(const float4*)&g_xf[(size_t)s2 * 128 + c];
        float4 v3 = *(const float4*)&g_xf[(size_t)s3 * 128 + c];
        acc.x = fmaxf(acc.x, fmaf(rz0, w2.x, fmaf(ry0, w1.x, fmaf(rx0, w0.x, v0.x))));
        acc.y = fmaxf(acc.y, fmaf(rz0, w2.y, fmaf(ry0, w1.y, fmaf(rx0, w0.y, v0.y))));
        acc.z = fmaxf(acc.z, fmaf(rz0, w2.z, fmaf(ry0, w1.z, fmaf(rx0, w0.z, v0.z))));
        acc.w = fmaxf(acc.w, fmaf(rz0, w2.w, fmaf(ry0, w1.w, fmaf(rx0, w0.w, v0.w))));
        acc.x = fmaxf(acc.x, fmaf(rz1, w2.x, fmaf(ry1, w1.x, fmaf(rx1, w0.x, v1.x))));
        acc.y = fmaxf(acc.y, fmaf(rz1, w2.y, fmaf(ry1, w1.y, fmaf(rx1, w0.y, v1.y))));
        acc.z = fmaxf(acc.z, fmaf(rz1, w2.z, fmaf(ry1, w1.z, fmaf(rx1, w0.z, v1.z))));
        acc.w = fmaxf(acc.w, fmaf(rz1, w2.w, fmaf(ry1, w1.w, fmaf(rx1, w0.w, v1.w))));
        acc.x = fmaxf(acc.x, fmaf(rz2, w2.x, fmaf(ry2, w1.x, fmaf(rx2, w0.x, v2.x))));
        acc.y = fmaxf(acc.y, fmaf(rz2, w2.y, fmaf(ry2, w1.y, fmaf(rx2, w0.y, v2.y))));
        acc.z = fmaxf(acc.z, fmaf(rz2, w2.z, fmaf(ry2, w1.z, fmaf(rx2, w0.z, v2.z))));
        acc.w = fmaxf(acc.w, fmaf(rz2, w2.w, fmaf(ry2, w1.w, fmaf(rx2, w0.w, v2.w))));
        acc.x = fmaxf(acc.x, fmaf(rz3, w2.x, fmaf(ry3, w1.x, fmaf(rx3, w0.x, v3.x))));
        acc.y = fmaxf(acc.y, fmaf(rz3, w2.y, fmaf(ry3, w1.y, fmaf(rx3, w0.y, v3.y))));
        acc.z = fmaxf(acc.z, fmaf(rz3, w2.z, fmaf(ry3, w1.z, fmaf(rx3, w0.z, v3.z))));
        acc.w = fmaxf(acc.w, fmaf(rz3, w2.w, fmaf(ry3, w1.w, fmaf(rx3, w0.w, v3.w))));
    }
    for (; p < p1; ++p) {
        int s = g_esrc[p];
        float rx = pos[s * 3 + 0] + bx, ry = pos[s * 3 + 1] + by, rz = pos[s * 3 + 2] + bz;
        float4 v = *(const float4*)&g_xf[(size_t)s * 128 + c];
        acc.x = fmaxf(acc.x, fmaf(rz, w2.x, fmaf(ry, w1.x, fmaf(rx, w0.x, v.x))));
        acc.y = fmaxf(acc.y, fmaf(rz, w2.y, fmaf(ry, w1.y, fmaf(rx, w0.y, v.y))));
        acc.z = fmaxf(acc.z, fmaf(rz, w2.z, fmaf(ry, w1.z, fmaf(rx, w0.z, v.z))));
        acc.w = fmaxf(acc.w, fmaf(rz, w2.w, fmaf(ry, w1.w, fmaf(rx, w0.w, v.w))));
    }
    float4 o;
    if (p1 > p0) {
        o.x = lrelu(acc.x); o.y = lrelu(acc.y);
        o.z = lrelu(acc.z); o.w = lrelu(acc.w);
    } else {
        o = make_float4(0.f, 0.f, 0.f, 0.f);
    }
    *(float4*)&g_agg[(size_t)warp * 128 + c] = o;
}

// ---------------- fused: out = lrelu(agg@Wg1+bg1)@Wg2 + bg2 + x ----------------
// Ts aliases Bs1 (Wg1 tile dead after mainloop); pitch 128, broadcast reads.
#define PADT2 128
__global__ __launch_bounds__(256, 1)
void gemm_out_kernel(const float* __restrict__ A, const float* __restrict__ B1,
                     const float* __restrict__ b1, const float* __restrict__ B2,
                     const float* __restrict__ b2, const float* __restrict__ X,
                     float* __restrict__ O, int M) {
    extern __shared__ float sm[];
    float* Bs1 = sm;                 // 16384 (becomes Ts after stage 1)
    float* Bs2 = sm + 16384;         // 16384
    float* As0 = sm + 32768;         // 4352
    float* As1 = As0 + 32 * PADA;    // 4352
    float* Ts  = Bs1;                // alias
    int tid = threadIdx.x, tx = tid & 15, ty = tid >> 4;
    int row0 = blockIdx.x * 128;

    #pragma unroll
    for (int it = 0; it < 16; ++it) {
        int idx = (it * 256 + tid) * 4;
        *(float4*)&Bs1[idx] = *(const float4*)&B1[idx];
        *(float4*)&Bs2[idx] = *(const float4*)&B2[idx];
    }
    unsigned long long acc[8][4];
    #pragma unroll
    for (int i = 0; i < 8; i++)
        #pragma unroll
        for (int j = 0; j < 4; j++) acc[i][j] = 0ull;

    gemm_core32(A, M, row0, Bs1, As0, As1, acc, tid, tx, ty);
    // gemm_core32's final __syncthreads makes Bs1 reads complete; safe to alias as Ts.

    {
        float4 bA = *(const float4*)&b1[tx * 4];
        float4 bB = *(const float4*)&b1[64 + tx * 4];
        #pragma unroll
        for (int i = 0; i < 8; i++) {
            int r = ty * 8 + i;
            float2 f0 = unpk(acc[i][0]), f1 = unpk(acc[i][1]);
            float2 f2 = unpk(acc[i][2]), f3 = unpk(acc[i][3]);
            *(float4*)&Ts[r * PADT2 + tx * 4] =
                make_float4(lrelu(f0.x + bA.x), lrelu(f0.y + bA.y),
                            lrelu(f1.x + bA.z), lrelu(f1.y + bA.w));
            *(float4*)&Ts[r * PADT2 + 64 + tx * 4] =
                make_float4(lrelu(f2.x + bB.x), lrelu(f2.y + bB.y),
                            lrelu(f3.x + bB.z), lrelu(f3.y + bB.w));
        }
    }
    __syncthreads();

    #pragma unroll
    for (int i = 0; i < 8; i++)
        #pragma unroll
        for (int j = 0; j < 4; j++) acc[i][j] = 0ull;

    #pragma unroll 4
    for (int k = 0; k < 128; k++) {
        const float* br = &Bs2[k * 128];
        ulonglong2 b01 = *(const ulonglong2*)&br[tx * 4];
        ulonglong2 b23 = *(const ulonglong2*)&br[64 + tx * 4];
        #pragma unroll
        for (int i = 0; i < 8; i++) {
            unsigned long long as_ = splat2(Ts[(ty * 8 + i) * PADT2 + k]);
            fma2(acc[i][0], as_, b01.x);
            fma2(acc[i][1], as_, b01.y);
            fma2(acc[i][2], as_, b23.x);
            fma2(acc[i][3], as_, b23.y);
        }
    }

    float4 bA = *(const float4*)&b2[tx * 4];
    float4 bB = *(const float4*)&b2[64 + tx * 4];
    #pragma unroll
    for (int i = 0; i < 8; i++) {
        int grow = row0 + ty * 8 + i;
        if (grow >= M) continue;
        float2 f0 = unpk(acc[i][0]), f1 = unpk(acc[i][1]);
        float2 f2 = unpk(acc[i][2]), f3 = unpk(acc[i][3]);
        float4 r0 = *(const float4*)&X[(size_t)grow * 128 + tx * 4];
        float4 r1 = *(const float4*)&X[(size_t)grow * 128 + 64 + tx * 4];
        *(float4*)&O[(size_t)grow * 128 + tx * 4] =
            make_float4(f0.x + bA.x + r0.x, f0.y + bA.y + r0.y,
                        f1.x + bA.z + r0.z, f1.y + bA.w + r0.w);
        *(float4*)&O[(size_t)grow * 128 + 64 + tx * 4] =
            make_float4(f2.x + bB.x + r1.x, f2.y + bB.y + r1.y,
                        f3.x + bB.z + r1.z, f3.y + bB.w + r1.w);
    }
}

// ---------------- launch ----------------
extern "C" void kernel_launch(void* const* d_in, const int* in_sizes, int n_in,
                              void* d_out, int out_size) {
    const float* x   = (const float*)d_in[0];
    const float* pos = (const float*)d_in[1];
    const void*  ei  = d_in[2];
    const float* Wh1 = (const float*)d_in[3];
    const float* bh1 = (const float*)d_in[4];
    const float* Wh2 = (const float*)d_in[5];
    const float* bh2 = (const float*)d_in[6];
    const float* Wf  = (const float*)d_in[7];
    const float* bf  = (const float*)d_in[8];
    const float* Wg1 = (const float*)d_in[9];
    const float* bg1 = (const float*)d_in[10];
    const float* Wg2 = (const float*)d_in[11];
    const float* bg2 = (const float*)d_in[12];
    float* out = (float*)d_out;

    int M = in_sizes[0] / CDIM;   // 50000
    int E = in_sizes[2] / 2;      // 800000

    const int SM_BIAS   = (16384 + 2 * 32 * PADA) * sizeof(float);
    const int SM_HDELTA = (16384 + 2 * 32 * PADA + 384 + 384) * sizeof(float);
    const int SM_OUT    = (16384 * 2 + 2 * 32 * PADA) * sizeof(float);
    cudaFuncSetAttribute(gemm_bias_kernel,   cudaFuncAttributeMaxDynamicSharedMemorySize, SM_BIAS);
    cudaFuncSetAttribute(gemm_hdelta_kernel, cudaFuncAttributeMaxDynamicSharedMemorySize, SM_HDELTA);
    cudaFuncSetAttribute(gemm_out_kernel,    cudaFuncAttributeMaxDynamicSharedMemorySize, SM_OUT);

    float *xfp, *aggp;
    cudaGetSymbolAddress((void**)&xfp,  g_xf);
    cudaGetSymbolAddress((void**)&aggp, g_agg);

    int gemm_blocks = (M + 127) / 128;
    int eblocks = (E + 255) / 256;
    int nblocks = (M + 255) / 256;
    int sblocks = (M + 1023) / 1024;
    int wblocks = (M + 7) / 8;

    static cudaStream_t s_side = nullptr;
    static cudaEvent_t  s_e0 = nullptr, s_e1 = nullptr;
    if (s_side == nullptr) {
        cudaStreamCreateWithFlags(&s_side, cudaStreamNonBlocking);
        cudaEventCreateWithFlags(&s_e0, cudaEventDisableTiming);
        cudaEventCreateWithFlags(&s_e1, cudaEventDisableTiming);
    }

    // fork: CSR build on side stream
    cudaEventRecord(s_e0, 0);
    cudaStreamWaitEvent(s_side, s_e0, 0);
    detect_kernel<<<1, 32, 0, s_side>>>((const unsigned int*)ei, E);
    zero_cnt_kernel<<<nblocks, 256, 0, s_side>>>(M);
    convert_hist_kernel<<<eblocks, 256, 0, s_side>>>(ei, E);
    scanA_kernel<<<sblocks, 1024, 0, s_side>>>(M);
    scanB_kernel<<<1, 64, 0, s_side>>>(sblocks);
    scanC_kernel<<<sblocks, 1024, 0, s_side>>>(M);
    scatter_kernel<<<eblocks, 256, 0, s_side>>>(E);
    cudaEventRecord(s_e1, s_side);

    // main stream: node GEMMs (serial)
    gemm_hdelta_kernel<<<gemm_blocks, 256, SM_HDELTA>>>(x, Wh1, bh1, Wh2, bh2, M);
    gemm_bias_kernel<<<gemm_blocks, 256, SM_BIAS>>>(x, Wf + 3 * 128, bf, xfp, M);

    // join, then aggregate + output MLP
    cudaStreamWaitEvent(0, s_e1, 0);
    agg_kernel<<<wblocks, 256>>>(pos, Wf, M);
    gemm_out_kernel<<<gemm_blocks, 256, SM_OUT>>>(aggp, Wg1, bg1, Wg2, bg2, x, out, M);
}

// round 9
// speedup vs baseline: 1.0922x; 1.0922x over previous
#include <cuda_runtime.h>
#include <math.h>
#include <stdint.h>

#define NMAX 50000
#define EMAX 800000
#define CDIM 128
#define PADA 136   // f32x2 core A pitch (floats)
#define PADT 132   // out-kernel t-tile pitch (floats)

// ---------------- device scratch ----------------
__device__ int   g_is64;
__device__ float g_xf [(size_t)NMAX * CDIM];
__device__ float g_agg[(size_t)NMAX * CDIM];
__device__ float g_delta[(size_t)NMAX * 3];
__device__ int   g_src [EMAX];
__device__ int   g_dst [EMAX];
__device__ int   g_esrc[EMAX];
__device__ int   g_cnt [NMAX];
__device__ int   g_cur [NMAX];
__device__ int   g_off [NMAX + 1];
__device__ int   g_bsum[64];
__device__ int   g_bpre[64];
// WfX pre-split bf16 hi/lo in mma fragment order: [8 ks][16 j][32 lane][2 regs]
__device__ unsigned int g_bfh[8192];
__device__ unsigned int g_bfl[8192];

// ---------------- helpers ----------------
__device__ __forceinline__ unsigned long long splat2(float a) {
    unsigned long long r;
    asm("mov.b64 %0, {%1, %1};" : "=l"(r) : "f"(a));
    return r;
}
__device__ __forceinline__ void fma2(unsigned long long& d, unsigned long long a, unsigned long long b) {
    asm("fma.rn.f32x2 %0, %1, %2, %0;" : "+l"(d) : "l"(a), "l"(b));
}
__device__ __forceinline__ float2 unpk(unsigned long long v) {
    float lo, hi;
    asm("mov.b64 {%0, %1}, %2;" : "=f"(lo), "=f"(hi) : "l"(v));
    return make_float2(lo, hi);
}
__device__ __forceinline__ float lrelu(float v) { return (v > 0.f) ? v : 0.01f * v; }
// pack bf16x2: low half = e0 (lower index), high half = e1
__device__ __forceinline__ unsigned int pack_bf2(float e0, float e1) {
    unsigned int r;
    asm("cvt.rn.bf16x2.f32 %0, %1, %2;" : "=r"(r) : "f"(e1), "f"(e0));
    return r;
}
__device__ __forceinline__ void mma_bf16(float acc[4],
                                         unsigned int a0, unsigned int a1, unsigned int a2, unsigned int a3,
                                         unsigned int b0, unsigned int b1) {
    asm("mma.sync.aligned.m16n8k16.row.col.f32.bf16.bf16.f32 "
        "{%0,%1,%2,%3}, {%4,%5,%6,%7}, {%8,%9}, {%0,%1,%2,%3};"
        : "+f"(acc[0]), "+f"(acc[1]), "+f"(acc[2]), "+f"(acc[3])
        : "r"(a0), "r"(a1), "r"(a2), "r"(a3), "r"(b0), "r"(b1));
}

// ---------------- dtype detection ----------------
__global__ void detect_kernel(const unsigned int* __restrict__ w, int E) {
    int nz = 0;
    int lim = 2 * E;
    for (int i = threadIdx.x; i < 256; i += 32) {
        int wi = 2 * i + 1;
        if (wi < lim) nz |= (w[wi] != 0u);
    }
    nz = __any_sync(0xffffffffu, nz);
    if (threadIdx.x == 0) g_is64 = nz ? 0 : 1;
}

__global__ void zero_cnt_kernel(int n) {
    int i = blockIdx.x * blockDim.x + threadIdx.x;
    if (i < n) { g_cnt[i] = 0; g_cur[i] = 0; }
}

__global__ void convert_hist_kernel(const void* __restrict__ ei, int E) {
    int i = blockIdx.x * blockDim.x + threadIdx.x;
    if (i >= E) return;
    int s, d;
    if (g_is64) {
        const long long* p = (const long long*)ei;
        s = (int)p[i];
        d = (int)p[E + i];
    } else {
        const int* p = (const int*)ei;
        s = p[i];
        d = p[E + i];
    }
    g_src[i] = s;
    g_dst[i] = d;
    atomicAdd(&g_cnt[d], 1);
}

// ---------------- hierarchical scan ----------------
__global__ void scanA_kernel(int n) {
    __shared__ int wsum[32];
    int tid = threadIdx.x, lane = tid & 31, wid = tid >> 5;
    int i = blockIdx.x * 1024 + tid;
    int v = (i < n) ? g_cnt[i] : 0;
    int x = v;
    #pragma unroll
    for (int d = 1; d < 32; d <<= 1) {
        int t = __shfl_up_sync(0xffffffffu, x, d);
        if (lane >= d) x += t;
    }
    if (lane == 31) wsum[wid] = x;
    __syncthreads();
    if (wid == 0) {
        int s = wsum[lane];
        #pragma unroll
        for (int d = 1; d < 32; d <<= 1) {
            int t = __shfl_up_sync(0xffffffffu, s, d);
            if (lane >= d) s += t;
        }
        wsum[lane] = s;
    }
    __syncthreads();
    if (wid > 0) x += wsum[wid - 1];
    if (i < n) g_off[i + 1] = x;
    if (tid == 1023) g_bsum[blockIdx.x] = x;
}

__global__ void scanB_kernel(int nb) {
    __shared__ int ws[2];
    int t = threadIdx.x, lane = t & 31, w = t >> 5;
    int v = (t < nb) ? g_bsum[t] : 0;
    int x = v;
    #pragma unroll
    for (int d = 1; d < 32; d <<= 1) {
        int u = __shfl_up_sync(0xffffffffu, x, d);
        if (lane >= d) x += u;
    }
    if (lane == 31) ws[w] = x;
    __syncthreads();
    if (w == 1) x += ws[0];
    if (t < nb) g_bpre[t] = x - v;
}

__global__ void scanC_kernel(int n) {
    int i = blockIdx.x * 1024 + threadIdx.x;
    int add = g_bpre[blockIdx.x];
    if (i < n) g_off[i + 1] += add;
    if (i == 0) g_off[0] = 0;
}

__global__ void scatter_kernel(int E) {
    int i = blockIdx.x * blockDim.x + threadIdx.x;
    if (i >= E) return;
    int d = g_dst[i];
    int p = g_off[d] + atomicAdd(&g_cur[d], 1);
    g_esrc[p] = g_src[i];
}

// ---------------- WfX prep: split bf16 hi/lo into mma fragment order ----------------
// Fragment slot idx = (ks*16 + j)*32 + lane, regs b0 (k rows 2c,2c+1) and b1 (+8).
__global__ void prep_wfx_kernel(const float* __restrict__ W) {
    int idx = blockIdx.x * 256 + threadIdx.x;   // 0..4095
    if (idx >= 4096) return;
    int t  = idx & 31;
    int j  = (idx >> 5) & 15;
    int ks = idx >> 9;
    int n  = j * 8 + (t >> 2);
    int k1 = ks * 16 + 2 * (t & 3);
    float w00 = W[k1 * 128 + n],       w01 = W[(k1 + 1) * 128 + n];
    float w10 = W[(k1 + 8) * 128 + n], w11 = W[(k1 + 9) * 128 + n];
    unsigned int h0 = pack_bf2(w00, w01);
    unsigned int h1 = pack_bf2(w10, w11);
    float hf00 = __uint_as_float(h0 << 16);
    float hf01 = __uint_as_float(h0 & 0xFFFF0000u);
    float hf10 = __uint_as_float(h1 << 16);
    float hf11 = __uint_as_float(h1 & 0xFFFF0000u);
    unsigned int l0 = pack_bf2(w00 - hf00, w01 - hf01);
    unsigned int l1 = pack_bf2(w10 - hf10, w11 - hf11);
    g_bfh[idx * 2 + 0] = h0;
    g_bfh[idx * 2 + 1] = h1;
    g_bfl[idx * 2 + 0] = l0;
    g_bfl[idx * 2 + 1] = l1;
}

// ---------------- xf = x @ WfX + bf via mma.sync bf16 3-product ----------------
#define APITCH 272    // bytes per A row in smem (136 bf16)
#define XF_SMEM (32768 * 2 + 34816 * 2 + 512)
__global__ __launch_bounds__(256, 1)
void xf_mma_kernel(const float* __restrict__ A, const float* __restrict__ bias,
                   float* __restrict__ O, int M) {
    extern __shared__ char smx[];
    unsigned int* Bh = (unsigned int*)smx;              // 8192 u32
    unsigned int* Bl = (unsigned int*)(smx + 32768);    // 8192 u32
    char* Ah = smx + 65536;                             // 128 x 272B
    char* Al = smx + 65536 + 34816;
    float* sbias = (float*)(smx + 65536 + 69632);
    int tid = threadIdx.x, lane = tid & 31, warp = tid >> 5;
    int row0 = blockIdx.x * 128;

    // stage B fragments (same for all CTAs; L2-resident)
    #pragma unroll
    for (int i = 0; i < 8; i++) {
        int idx = i * 256 + tid;    // 2048 uint4
        ((uint4*)Bh)[idx] = ((const uint4*)g_bfh)[idx];
        ((uint4*)Bl)[idx] = ((const uint4*)g_bfl)[idx];
    }
    if (tid < 128) sbias[tid] = bias[tid];

    // stage A tile split hi/lo
    #pragma unroll
    for (int it = 0; it < 16; it++) {
        int idx = it * 256 + tid;   // 4096 float4 groups
        int r  = idx >> 5;
        int c4 = (idx & 31) * 4;
        float4 v = make_float4(0.f, 0.f, 0.f, 0.f);
        if (row0 + r < M) v = *(const float4*)&A[(size_t)(row0 + r) * 128 + c4];
        unsigned int h01 = pack_bf2(v.x, v.y);
        unsigned int h23 = pack_bf2(v.z, v.w);
        float hf0 = __uint_as_float(h01 << 16);
        float hf1 = __uint_as_float(h01 & 0xFFFF0000u);
        float hf2 = __uint_as_float(h23 << 16);
        float hf3 = __uint_as_float(h23 & 0xFFFF0000u);
        unsigned int l01 = pack_bf2(v.x - hf0, v.y - hf1);
        unsigned int l23 = pack_bf2(v.z - hf2, v.w - hf3);
        *(uint2*)(Ah + r * APITCH + c4 * 2) = make_uint2(h01, h23);
        *(uint2*)(Al + r * APITCH + c4 * 2) = make_uint2(l01, l23);
    }
    __syncthreads();

    float acc[16][4];
    #pragma unroll
    for (int j = 0; j < 16; j++)
        #pragma unroll
        for (int q = 0; q < 4; q++) acc[j][q] = 0.f;

    int gr  = lane >> 2;           // 0..7
    int cc2 = (lane & 3) * 2;      // 0,2,4,6
    int abase = (warp * 16 + gr) * APITCH + cc2 * 2;

    #pragma unroll
    for (int ks = 0; ks < 8; ks++) {
        int ao = abase + ks * 32;  // ks*16 elements * 2B
        unsigned int ah0 = *(unsigned int*)(Ah + ao);
        unsigned int ah1 = *(unsigned int*)(Ah + ao + 8 * APITCH);
        unsigned int ah2 = *(unsigned int*)(Ah + ao + 16);
        unsigned int ah3 = *(unsigned int*)(Ah + ao + 8 * APITCH + 16);
        unsigned int al0 = *(unsigned int*)(Al + ao);
        unsigned int al1 = *(unsigned int*)(Al + ao + 8 * APITCH);
        unsigned int al2 = *(unsigned int*)(Al + ao + 16);
        unsigned int al3 = *(unsigned int*)(Al + ao + 8 * APITCH + 16);
        #pragma unroll
        for (int jb = 0; jb < 4; jb++) {
            unsigned int bh[4][2], bl[4][2];
            #pragma unroll
            for (int q = 0; q < 4; q++) {
                int slot = ((ks * 16 + jb * 4 + q) * 32 + lane) * 2;
                uint2 t1 = *(uint2*)&Bh[slot];
                uint2 t2 = *(uint2*)&Bl[slot];
                bh[q][0] = t1.x; bh[q][1] = t1.y;
                bl[q][0] = t2.x; bl[q][1] = t2.y;
            }
            #pragma unroll
            for (int q = 0; q < 4; q++)
                mma_bf16(acc[jb * 4 + q], ah0, ah1, ah2, ah3, bh[q][0], bh[q][1]);
            #pragma unroll
            for (int q = 0; q < 4; q++)
                mma_bf16(acc[jb * 4 + q], ah0, ah1, ah2, ah3, bl[q][0], bl[q][1]);
            #pragma unroll
            for (int q = 0; q < 4; q++)
                mma_bf16(acc[jb * 4 + q], al0, al1, al2, al3, bh[q][0], bh[q][1]);
        }
    }

    // epilogue: + bias -> g_xf
    int r1 = row0 + warp * 16 + gr;
    #pragma unroll
    for (int j = 0; j < 16; j++) {
        int col = j * 8 + cc2;
        float b0 = sbias[col], b1 = sbias[col + 1];
        if (r1 < M)
            *(float2*)&O[(size_t)r1 * 128 + col] = make_float2(acc[j][0] + b0, acc[j][1] + b1);
        if (r1 + 8 < M)
            *(float2*)&O[(size_t)(r1 + 8) * 128 + col] = make_float2(acc[j][2] + b0, acc[j][3] + b1);
    }
}

// ---------------- f32x2 GEMM core (R7 version: 16-chunk, reg prefetch) ----------------
__device__ __forceinline__ void gemm_core(
    const float* __restrict__ A, int M, int row0,
    const float* Bs, float* As, unsigned long long acc[8][4],
    int tid, int tx, int ty)
{
    int r_ = tid >> 2;
    int c_ = (tid & 3) * 4;
    int g0 = row0 + r_;
    int g1 = row0 + 64 + r_;
    const float* A0 = &A[(size_t)g0 * 128 + c_];
    const float* A1 = &A[(size_t)g1 * 128 + c_];
    bool ok0 = g0 < M, ok1 = g1 < M;

    float4 v0 = make_float4(0.f, 0.f, 0.f, 0.f);
    float4 v1 = make_float4(0.f, 0.f, 0.f, 0.f);
    if (ok0) v0 = *(const float4*)A0;
    if (ok1) v1 = *(const float4*)A1;

    #pragma unroll
    for (int k0 = 0; k0 < 128; k0 += 16) {
        As[(c_ + 0) * PADA + r_] = v0.x;
        As[(c_ + 1) * PADA + r_] = v0.y;
        As[(c_ + 2) * PADA + r_] = v0.z;
        As[(c_ + 3) * PADA + r_] = v0.w;
        As[(c_ + 0) * PADA + 64 + r_] = v1.x;
        As[(c_ + 1) * PADA + 64 + r_] = v1.y;
        As[(c_ + 2) * PADA + 64 + r_] = v1.z;
        As[(c_ + 3) * PADA + 64 + r_] = v1.w;
        if (k0 < 112) {
            v0 = make_float4(0.f, 0.f, 0.f, 0.f);
            v1 = make_float4(0.f, 0.f, 0.f, 0.f);
            if (ok0) v0 = *(const float4*)(A0 + k0 + 16);
            if (ok1) v1 = *(const float4*)(A1 + k0 + 16);
        }
        __syncthreads();
        #pragma unroll
        for (int k = 0; k < 16; k++) {
            float4 a0 = *(float4*)&As[k * PADA + ty * 8];
            float4 a1 = *(float4*)&As[k * PADA + ty * 8 + 4];
            const float* br = &Bs[(k0 + k) * 128];
            ulonglong2 b01 = *(const ulonglong2*)&br[tx * 4];
            ulonglong2 b23 = *(const ulonglong2*)&br[64 + tx * 4];
            float av[8] = {a0.x, a0.y, a0.z, a0.w, a1.x, a1.y, a1.z, a1.w};
            #pragma unroll
            for (int i = 0; i < 8; i++) {
                unsigned long long as_ = splat2(av[i]);
                fma2(acc[i][0], as_, b01.x);
                fma2(acc[i][1], as_, b01.y);
                fma2(acc[i][2], as_, b23.x);
                fma2(acc[i][3], as_, b23.y);
            }
        }
        __syncthreads();
    }
}

// ---------------- delta = tanh(lrelu(x@Wh1+bh1) @ Wh2 + bh2), fused ----------------
__global__ __launch_bounds__(256, 2)
void gemm_hdelta_kernel(const float* __restrict__ A, const float* __restrict__ B,
                        const float* __restrict__ bias,
                        const float* __restrict__ Wh2, const float* __restrict__ bh2, int M) {
    extern __shared__ float sm[];
    float* Bs   = sm;
    float* As   = sm + 16384;
    float* sW2  = sm + 16384 + 2176;
    float* sdel = sm + 16384 + 2176 + 384;
    int tid = threadIdx.x, tx = tid & 15, ty = tid >> 4;
    int row0 = blockIdx.x * 128;

    #pragma unroll
    for (int it = 0; it < 16; ++it) {
        int idx = (it * 256 + tid) * 4;
        *(float4*)&Bs[idx] = *(const float4*)&B[idx];
    }
    if (tid < 96) *(float4*)&sW2[tid * 4] = *(const float4*)&Wh2[tid * 4];

    unsigned long long acc[8][4];
    #pragma unroll
    for (int i = 0; i < 8; i++)
        #pragma unroll
        for (int j = 0; j < 4; j++) acc[i][j] = 0ull;

    gemm_core(A, M, row0, Bs, As, acc, tid, tx, ty);

    float4 bA = *(const float4*)&bias[tx * 4];
    float4 bB = *(const float4*)&bias[64 + tx * 4];
    float bb[8] = {bA.x, bA.y, bA.z, bA.w, bB.x, bB.y, bB.z, bB.w};

    #pragma unroll
    for (int i = 0; i < 8; i++) {
        float p0 = 0.f, p1 = 0.f, p2 = 0.f;
        #pragma unroll
        for (int j = 0; j < 4; j++) {
            int c0 = (j < 2) ? (tx * 4 + j * 2) : (64 + tx * 4 + (j - 2) * 2);
            float2 f = unpk(acc[i][j]);
            f.x = lrelu(f.x + bb[j * 2 + 0]);
            f.y = lrelu(f.y + bb[j * 2 + 1]);
            p0 += f.x * sW2[c0 * 3 + 0] + f.y * sW2[(c0 + 1) * 3 + 0];
            p1 += f.x * sW2[c0 * 3 + 1] + f.y * sW2[(c0 + 1) * 3 + 1];
            p2 += f.x * sW2[c0 * 3 + 2] + f.y * sW2[(c0 + 1) * 3 + 2];
        }
        #pragma unroll
        for (int d = 1; d < 16; d <<= 1) {
            p0 += __shfl_xor_sync(0xffffffffu, p0, d);
            p1 += __shfl_xor_sync(0xffffffffu, p1, d);
            p2 += __shfl_xor_sync(0xffffffffu, p2, d);
        }
        if (tx == 0) {
            int r = ty * 8 + i;
            sdel[r * 3 + 0] = p0;
            sdel[r * 3 + 1] = p1;
            sdel[r * 3 + 2] = p2;
        }
    }
    __syncthreads();
    if (tid < 128) {
        int grow = row0 + tid;
        if (grow < M) {
            g_delta[grow * 3 + 0] = tanhf(sdel[tid * 3 + 0] + bh2[0]);
            g_delta[grow * 3 + 1] = tanhf(sdel[tid * 3 + 1] + bh2[1]);
            g_delta[grow * 3 + 2] = tanhf(sdel[tid * 3 + 2] + bh2[2]);
        }
    }
}

// ---------------- edge aggregation: warp per dst node, unroll 4 ----------------
__global__ void agg_kernel(const float* __restrict__ pos, const float* __restrict__ Wf, int N) {
    int warp = (blockIdx.x * blockDim.x + threadIdx.x) >> 5;
    int lane = threadIdx.x & 31;
    if (warp >= N) return;
    int c = lane * 4;
    float4 w0 = *(const float4*)&Wf[c];
    float4 w1 = *(const float4*)&Wf[128 + c];
    float4 w2 = *(const float4*)&Wf[256 + c];
    float bx = g_delta[warp * 3 + 0] - pos[warp * 3 + 0];
    float by = g_delta[warp * 3 + 1] - pos[warp * 3 + 1];
    float bz = g_delta[warp * 3 + 2] - pos[warp * 3 + 2];
    int p0 = g_off[warp], p1 = g_off[warp + 1];
    float4 acc = make_float4(-INFINITY, -INFINITY, -INFINITY, -INFINITY);
    int p = p0;
    for (; p + 4 <= p1; p += 4) {
        int s0 = g_esrc[p + 0];
        int s1 = g_esrc[p + 1];
        int s2 = g_esrc[p + 2];
        int s3 = g_esrc[p + 3];
        float rx0 = pos[s0 * 3 + 0] + bx, ry0 = pos[s0 * 3 + 1] + by, rz0 = pos[s0 * 3 + 2] + bz;
        float rx1 = pos[s1 * 3 + 0] + bx, ry1 = pos[s1 * 3 + 1] + by, rz1 = pos[s1 * 3 + 2] + bz;
        float rx2 = pos[s2 * 3 + 0] + bx, ry2 = pos[s2 * 3 + 1] + by, rz2 = pos[s2 * 3 + 2] + bz;
        float rx3 = pos[s3 * 3 + 0] + bx, ry3 = pos[s3 * 3 + 1] + by, rz3 = pos[s3 * 3 + 2] + bz;
        float4 v0 = *(const float4*)&g_xf[(size_t)s0 * 128 + c];
        float4 v1 = *(const float4*)&g_xf[(size_t)s1 * 128 + c];
        float4 v2 = *(const float4*)&g_xf[(size_t)s2 * 128 + c];
        float4 v3 = *(const float4*)&g_xf[(size_t)s3 * 128 + c];
        acc.x = fmaxf(acc.x, fmaf(rz0, w2.x, fmaf(ry0, w1.x, fmaf(rx0, w0.x, v0.x))));
        acc.y = fmaxf(acc.y, fmaf(rz0, w2.y, fmaf(ry0, w1.y, fmaf(rx0, w0.y, v0.y))));
        acc.z = fmaxf(acc.z, fmaf(rz0, w2.z, fmaf(ry0, w1.z, fmaf(rx0, w0.z, v0.z))));
        acc.w = fmaxf(acc.w, fmaf(rz0, w2.w, fmaf(ry0, w1.w, fmaf(rx0, w0.w, v0.w))));
        acc.x = fmaxf(acc.x, fmaf(rz1, w2.x, fmaf(ry1, w1.x, fmaf(rx1, w0.x, v1.x))));
        acc.y = fmaxf(acc.y, fmaf(rz1, w2.y, fmaf(ry1, w1.y, fmaf(rx1, w0.y, v1.y))));
        acc.z = fmaxf(acc.z, fmaf(rz1, w2.z, fmaf(ry1, w1.z, fmaf(rx1, w0.z, v1.z))));
        acc.w = fmaxf(acc.w, fmaf(rz1, w2.w, fmaf(ry1, w1.w, fmaf(rx1, w0.w, v1.w))));
        acc.x = fmaxf(acc.x, fmaf(rz2, w2.x, fmaf(ry2, w1.x, fmaf(rx2, w0.x, v2.x))));
        acc.y = fmaxf(acc.y, fmaf(rz2, w2.y, fmaf(ry2, w1.y, fmaf(rx2, w0.y, v2.y))));
        acc.z = fmaxf(acc.z, fmaf(rz2, w2.z, fmaf(ry2, w1.z, fmaf(rx2, w0.z, v2.z))));
        acc.w = fmaxf(acc.w, fmaf(rz2, w2.w, fmaf(ry2, w1.w, fmaf(rx2, w0.w, v2.w))));
        acc.x = fmaxf(acc.x, fmaf(rz3, w2.x, fmaf(ry3, w1.x, fmaf(rx3, w0.x, v3.x))));
        acc.y = fmaxf(acc.y, fmaf(rz3, w2.y, fmaf(ry3, w1.y, fmaf(rx3, w0.y, v3.y))));
        acc.z = fmaxf(acc.z, fmaf(rz3, w2.z, fmaf(ry3, w1.z, fmaf(rx3, w0.z, v3.z))));
        acc.w = fmaxf(acc.w, fmaf(rz3, w2.w, fmaf(ry3, w1.w, fmaf(rx3, w0.w, v3.w))));
    }
    for (; p < p1; ++p) {
        int s = g_esrc[p];
        float rx = pos[s * 3 + 0] + bx, ry = pos[s * 3 + 1] + by, rz = pos[s * 3 + 2] + bz;
        float4 v = *(const float4*)&g_xf[(size_t)s * 128 + c];
        acc.x = fmaxf(acc.x, fmaf(rz, w2.x, fmaf(ry, w1.x, fmaf(rx, w0.x, v.x))));
        acc.y = fmaxf(acc.y, fmaf(rz, w2.y, fmaf(ry, w1.y, fmaf(rx, w0.y, v.y))));
        acc.z = fmaxf(acc.z, fmaf(rz, w2.z, fmaf(ry, w1.z, fmaf(rx, w0.z, v.z))));
        acc.w = fmaxf(acc.w, fmaf(rz, w2.w, fmaf(ry, w1.w, fmaf(rx, w0.w, v.w))));
    }
    float4 o;
    if (p1 > p0) {
        o.x = lrelu(acc.x); o.y = lrelu(acc.y);
        o.z = lrelu(acc.z); o.w = lrelu(acc.w);
    } else {
        o = make_float4(0.f, 0.f, 0.f, 0.f);
    }
    *(float4*)&g_agg[(size_t)warp * 128 + c] = o;
}

// ---------------- fused: out = lrelu(agg@Wg1+bg1)@Wg2 + bg2 + x ----------------
__global__ __launch_bounds__(256, 1)
void gemm_out_kernel(const float* __restrict__ A, const float* __restrict__ B1,
                     const float* __restrict__ b1, const float* __restrict__ B2,
                     const float* __restrict__ b2, const float* __restrict__ X,
                     float* __restrict__ O, int M) {
    extern __shared__ float sm[];
    float* Bs1 = sm;
    float* Bs2 = sm + 16384;
    float* Ts  = sm + 32768;
    float* As  = sm + 32768 + 16896;
    int tid = threadIdx.x, tx = tid & 15, ty = tid >> 4;
    int row0 = blockIdx.x * 128;

    #pragma unroll
    for (int it = 0; it < 16; ++it) {
        int idx = (it * 256 + tid) * 4;
        *(float4*)&Bs1[idx] = *(const float4*)&B1[idx];
        *(float4*)&Bs2[idx] = *(const float4*)&B2[idx];
    }
    unsigned long long acc[8][4];
    #pragma unroll
    for (int i = 0; i < 8; i++)
        #pragma unroll
        for (int j = 0; j < 4; j++) acc[i][j] = 0ull;

    gemm_core(A, M, row0, Bs1, As, acc, tid, tx, ty);

    {
        float4 bA = *(const float4*)&b1[tx * 4];
        float4 bB = *(const float4*)&b1[64 + tx * 4];
        #pragma unroll
        for (int i = 0; i < 8; i++) {
            int r = ty * 8 + i;
            float2 f0 = unpk(acc[i][0]), f1 = unpk(acc[i][1]);
            float2 f2 = unpk(acc[i][2]), f3 = unpk(acc[i][3]);
            *(float4*)&Ts[r * PADT + tx * 4] =
                make_float4(lrelu(f0.x + bA.x), lrelu(f0.y + bA.y),
                            lrelu(f1.x + bA.z), lrelu(f1.y + bA.w));
            *(float4*)&Ts[r * PADT + 64 + tx * 4] =
                make_float4(lrelu(f2.x + bB.x), lrelu(f2.y + bB.y),
                            lrelu(f3.x + bB.z), lrelu(f3.y + bB.w));
        }
    }
    __syncthreads();

    #pragma unroll
    for (int i = 0; i < 8; i++)
        #pragma unroll
        for (int j = 0; j < 4; j++) acc[i][j] = 0ull;

    #pragma unroll 4
    for (int k = 0; k < 128; k++) {
        const float* br = &Bs2[k * 128];
        ulonglong2 b01 = *(const ulonglong2*)&br[tx * 4];
        ulonglong2 b23 = *(const ulonglong2*)&br[64 + tx * 4];
        #pragma unroll
        for (int i = 0; i < 8; i++) {
            unsigned long long as_ = splat2(Ts[(ty * 8 + i) * PADT + k]);
            fma2(acc[i][0], as_, b01.x);
            fma2(acc[i][1], as_, b01.y);
            fma2(acc[i][2], as_, b23.x);
            fma2(acc[i][3], as_, b23.y);
        }
    }

    float4 bA = *(const float4*)&b2[tx * 4];
    float4 bB = *(const float4*)&b2[64 + tx * 4];
    #pragma unroll
    for (int i = 0; i < 8; i++) {
        int grow = row0 + ty * 8 + i;
        if (grow >= M) continue;
        float2 f0 = unpk(acc[i][0]), f1 = unpk(acc[i][1]);
        float2 f2 = unpk(acc[i][2]), f3 = unpk(acc[i][3]);
        float4 r0 = *(const float4*)&X[(size_t)grow * 128 + tx * 4];
        float4 r1 = *(const float4*)&X[(size_t)grow * 128 + 64 + tx * 4];
        *(float4*)&O[(size_t)grow * 128 + tx * 4] =
            make_float4(f0.x + bA.x + r0.x, f0.y + bA.y + r0.y,
                        f1.x + bA.z + r0.z, f1.y + bA.w + r0.w);
        *(float4*)&O[(size_t)grow * 128 + 64 + tx * 4] =
            make_float4(f2.x + bB.x + r1.x, f2.y + bB.y + r1.y,
                        f3.x + bB.z + r1.z, f3.y + bB.w + r1.w);
    }
}

// ---------------- launch ----------------
extern "C" void kernel_launch(void* const* d_in, const int* in_sizes, int n_in,
                              void* d_out, int out_size) {
    const float* x   = (const float*)d_in[0];
    const float* pos = (const float*)d_in[1];
    const void*  ei  = d_in[2];
    const float* Wh1 = (const float*)d_in[3];
    const float* bh1 = (const float*)d_in[4];
    const float* Wh2 = (const float*)d_in[5];
    const float* bh2 = (const float*)d_in[6];
    const float* Wf  = (const float*)d_in[7];
    const float* bf  = (const float*)d_in[8];
    const float* Wg1 = (const float*)d_in[9];
    const float* bg1 = (const float*)d_in[10];
    const float* Wg2 = (const float*)d_in[11];
    const float* bg2 = (const float*)d_in[12];
    float* out = (float*)d_out;

    int M = in_sizes[0] / CDIM;   // 50000
    int E = in_sizes[2] / 2;      // 800000

    const int SM_HDELTA = (16384 + 16 * PADA + 384 + 128 * 3) * sizeof(float);
    const int SM_OUT    = (16384 * 2 + 128 * PADT + 16 * PADA) * sizeof(float);
    cudaFuncSetAttribute(xf_mma_kernel,      cudaFuncAttributeMaxDynamicSharedMemorySize, XF_SMEM);
    cudaFuncSetAttribute(gemm_hdelta_kernel, cudaFuncAttributeMaxDynamicSharedMemorySize, SM_HDELTA);
    cudaFuncSetAttribute(gemm_out_kernel,    cudaFuncAttributeMaxDynamicSharedMemorySize, SM_OUT);

    float *xfp, *aggp;
    cudaGetSymbolAddress((void**)&xfp,  g_xf);
    cudaGetSymbolAddress((void**)&aggp, g_agg);

    int gemm_blocks = (M + 127) / 128;
    int eblocks = (E + 255) / 256;
    int nblocks = (M + 255) / 256;
    int sblocks = (M + 1023) / 1024;
    int wblocks = (M + 7) / 8;

    static cudaStream_t s_side = nullptr;
    static cudaEvent_t  s_e0 = nullptr, s_e1 = nullptr;
    if (s_side == nullptr) {
        cudaStreamCreateWithFlags(&s_side, cudaStreamNonBlocking);
        cudaEventCreateWithFlags(&s_e0, cudaEventDisableTiming);
        cudaEventCreateWithFlags(&s_e1, cudaEventDisableTiming);
    }

    // main: weight prep for xf mma (launch idx 0)
    prep_wfx_kernel<<<16, 256>>>(Wf + 3 * 128);

    // fork: CSR build on side stream (idx 1..4)
    cudaEventRecord(s_e0, 0);
    cudaStreamWaitEvent(s_side, s_e0, 0);
    detect_kernel<<<1, 32, 0, s_side>>>((const unsigned int*)ei, E);
    zero_cnt_kernel<<<nblocks, 256, 0, s_side>>>(M);
    convert_hist_kernel<<<eblocks, 256, 0, s_side>>>(ei, E);
    scanA_kernel<<<sblocks, 1024, 0, s_side>>>(M);

    // main: xf mma GEMM (launch idx 5 — ncu capture target)
    xf_mma_kernel<<<gemm_blocks, 256, XF_SMEM>>>(x, bf, xfp, M);

    // side: rest of CSR
    scanB_kernel<<<1, 64, 0, s_side>>>(sblocks);
    scanC_kernel<<<sblocks, 1024, 0, s_side>>>(M);
    scatter_kernel<<<eblocks, 256, 0, s_side>>>(E);
    cudaEventRecord(s_e1, s_side);

    // main: hdelta GEMM (f32x2)
    gemm_hdelta_kernel<<<gemm_blocks, 256, SM_HDELTA>>>(x, Wh1, bh1, Wh2, bh2, M);

    // join, then aggregate + output MLP
    cudaStreamWaitEvent(0, s_e1, 0);
    agg_kernel<<<wblocks, 256>>>(pos, Wf, M);
    gemm_out_kernel<<<gemm_blocks, 256, SM_OUT>>>(aggp, Wg1, bg1, Wg2, bg2, x, out, M);
}

// round 10
// speedup vs baseline: 1.5672x; 1.4350x over previous
#include <cuda_runtime.h>
#include <math.h>
#include <stdint.h>

#define NMAX 50000
#define EMAX 800000
#define CDIM 128

// ---------------- device scratch ----------------
__device__ int   g_is64;
__device__ float g_xf [(size_t)NMAX * CDIM];
__device__ float g_agg[(size_t)NMAX * CDIM];
__device__ float g_delta[(size_t)NMAX * 3];
__device__ int   g_src [EMAX];
__device__ int   g_dst [EMAX];
__device__ int   g_esrc[EMAX];
__device__ int   g_cnt [NMAX];
__device__ int   g_cur [NMAX];
__device__ int   g_off [NMAX + 1];
__device__ int   g_bsum[64];
__device__ int   g_bpre[64];
// weights pre-split bf16 hi/lo in mma fragment order: [w][8 ks][16 j][32 lane][2 regs]
// w: 0=Wh1 1=WfX 2=Wg1 3=Wg2
__device__ unsigned int g_bfh[4][8192];
__device__ unsigned int g_bfl[4][8192];

// ---------------- helpers ----------------
__device__ __forceinline__ float lrelu(float v) { return (v > 0.f) ? v : 0.01f * v; }
// pack bf16x2: low half = e0 (lower index), high half = e1
__device__ __forceinline__ unsigned int pack_bf2(float e0, float e1) {
    unsigned int r;
    asm("cvt.rn.bf16x2.f32 %0, %1, %2;" : "=r"(r) : "f"(e1), "f"(e0));
    return r;
}
__device__ __forceinline__ void mma_bf16(float acc[4],
                                         unsigned int a0, unsigned int a1, unsigned int a2, unsigned int a3,
                                         unsigned int b0, unsigned int b1) {
    asm("mma.sync.aligned.m16n8k16.row.col.f32.bf16.bf16.f32 "
        "{%0,%1,%2,%3}, {%4,%5,%6,%7}, {%8,%9}, {%0,%1,%2,%3};"
        : "+f"(acc[0]), "+f"(acc[1]), "+f"(acc[2]), "+f"(acc[3])
        : "r"(a0), "r"(a1), "r"(a2), "r"(a3), "r"(b0), "r"(b1));
}

// ---------------- dtype detection ----------------
__global__ void detect_kernel(const unsigned int* __restrict__ w, int E) {
    int nz = 0;
    int lim = 2 * E;
    for (int i = threadIdx.x; i < 256; i += 32) {
        int wi = 2 * i + 1;
        if (wi < lim) nz |= (w[wi] != 0u);
    }
    nz = __any_sync(0xffffffffu, nz);
    if (threadIdx.x == 0) g_is64 = nz ? 0 : 1;
}

__global__ void zero_cnt_kernel(int n) {
    int i = blockIdx.x * blockDim.x + threadIdx.x;
    if (i < n) { g_cnt[i] = 0; g_cur[i] = 0; }
}

__global__ void convert_hist_kernel(const void* __restrict__ ei, int E) {
    int i = blockIdx.x * blockDim.x + threadIdx.x;
    if (i >= E) return;
    int s, d;
    if (g_is64) {
        const long long* p = (const long long*)ei;
        s = (int)p[i];
        d = (int)p[E + i];
    } else {
        const int* p = (const int*)ei;
        s = p[i];
        d = p[E + i];
    }
    g_src[i] = s;
    g_dst[i] = d;
    atomicAdd(&g_cnt[d], 1);
}

// ---------------- hierarchical scan ----------------
__global__ void scanA_kernel(int n) {
    __shared__ int wsum[32];
    int tid = threadIdx.x, lane = tid & 31, wid = tid >> 5;
    int i = blockIdx.x * 1024 + tid;
    int v = (i < n) ? g_cnt[i] : 0;
    int x = v;
    #pragma unroll
    for (int d = 1; d < 32; d <<= 1) {
        int t = __shfl_up_sync(0xffffffffu, x, d);
        if (lane >= d) x += t;
    }
    if (lane == 31) wsum[wid] = x;
    __syncthreads();
    if (wid == 0) {
        int s = wsum[lane];
        #pragma unroll
        for (int d = 1; d < 32; d <<= 1) {
            int t = __shfl_up_sync(0xffffffffu, s, d);
            if (lane >= d) s += t;
        }
        wsum[lane] = s;
    }
    __syncthreads();
    if (wid > 0) x += wsum[wid - 1];
    if (i < n) g_off[i + 1] = x;
    if (tid == 1023) g_bsum[blockIdx.x] = x;
}

__global__ void scanB_kernel(int nb) {
    __shared__ int ws[2];
    int t = threadIdx.x, lane = t & 31, w = t >> 5;
    int v = (t < nb) ? g_bsum[t] : 0;
    int x = v;
    #pragma unroll
    for (int d = 1; d < 32; d <<= 1) {
        int u = __shfl_up_sync(0xffffffffu, x, d);
        if (lane >= d) x += u;
    }
    if (lane == 31) ws[w] = x;
    __syncthreads();
    if (w == 1) x += ws[0];
    if (t < nb) g_bpre[t] = x - v;
}

__global__ void scanC_kernel(int n) {
    int i = blockIdx.x * 1024 + threadIdx.x;
    int add = g_bpre[blockIdx.x];
    if (i < n) g_off[i + 1] += add;
    if (i == 0) g_off[0] = 0;
}

__global__ void scatter_kernel(int E) {
    int i = blockIdx.x * blockDim.x + threadIdx.x;
    if (i >= E) return;
    int d = g_dst[i];
    int p = g_off[d] + atomicAdd(&g_cur[d], 1);
    g_esrc[p] = g_src[i];
}

// ---------------- weight prep: split bf16 hi/lo into mma fragment order ----------------
// Fragment slot idx = (ks*16 + j)*32 + lane; reg0 covers k rows (ks*16+2c, +1), reg1 +8.
__global__ void prep_w_kernel(const float* __restrict__ Wh1, const float* __restrict__ WfX,
                              const float* __restrict__ Wg1, const float* __restrict__ Wg2) {
    const float* W = (blockIdx.y == 0) ? Wh1 : (blockIdx.y == 1) ? WfX :
                     (blockIdx.y == 2) ? Wg1 : Wg2;
    int idx = blockIdx.x * 256 + threadIdx.x;   // 0..4095
    if (idx >= 4096) return;
    int t  = idx & 31;
    int j  = (idx >> 5) & 15;
    int ks = idx >> 9;
    int n  = j * 8 + (t >> 2);
    int k1 = ks * 16 + 2 * (t & 3);
    float w00 = W[k1 * 128 + n],       w01 = W[(k1 + 1) * 128 + n];
    float w10 = W[(k1 + 8) * 128 + n], w11 = W[(k1 + 9) * 128 + n];
    unsigned int h0 = pack_bf2(w00, w01);
    unsigned int h1 = pack_bf2(w10, w11);
    float hf00 = __uint_as_float(h0 << 16);
    float hf01 = __uint_as_float(h0 & 0xFFFF0000u);
    float hf10 = __uint_as_float(h1 << 16);
    float hf11 = __uint_as_float(h1 & 0xFFFF0000u);
    unsigned int l0 = pack_bf2(w00 - hf00, w01 - hf01);
    unsigned int l1 = pack_bf2(w10 - hf10, w11 - hf11);
    g_bfh[blockIdx.y][idx * 2 + 0] = h0;
    g_bfh[blockIdx.y][idx * 2 + 1] = h1;
    g_bfl[blockIdx.y][idx * 2 + 0] = l0;
    g_bfl[blockIdx.y][idx * 2 + 1] = l1;
}

// ---------------- shared mma building blocks ----------------
#define APITCH 272    // bytes per A row in smem (136 bf16)

// stage fp32 A tile [128,128] from gmem, split hi/lo bf16 into Ah/Al
__device__ __forceinline__ void stage_A_split(const float* __restrict__ A, int row0, int M,
                                              char* Ah, char* Al, int tid) {
    #pragma unroll
    for (int it = 0; it < 16; it++) {
        int idx = it * 256 + tid;
        int r  = idx >> 5;
        int c4 = (idx & 31) * 4;
        float4 v = make_float4(0.f, 0.f, 0.f, 0.f);
        if (row0 + r < M) v = *(const float4*)&A[(size_t)(row0 + r) * 128 + c4];
        unsigned int h01 = pack_bf2(v.x, v.y);
        unsigned int h23 = pack_bf2(v.z, v.w);
        float hf0 = __uint_as_float(h01 << 16);
        float hf1 = __uint_as_float(h01 & 0xFFFF0000u);
        float hf2 = __uint_as_float(h23 << 16);
        float hf3 = __uint_as_float(h23 & 0xFFFF0000u);
        unsigned int l01 = pack_bf2(v.x - hf0, v.y - hf1);
        unsigned int l23 = pack_bf2(v.z - hf2, v.w - hf3);
        *(uint2*)(Ah + r * APITCH + c4 * 2) = make_uint2(h01, h23);
        *(uint2*)(Al + r * APITCH + c4 * 2) = make_uint2(l01, l23);
    }
}

// stage B fragments from gmem fragment arrays
__device__ __forceinline__ void stage_B(const unsigned int* __restrict__ fh,
                                        const unsigned int* __restrict__ fl,
                                        unsigned int* Bh, unsigned int* Bl, int tid) {
    #pragma unroll
    for (int i = 0; i < 8; i++) {
        int idx = i * 256 + tid;    // 2048 uint4
        ((uint4*)Bh)[idx] = ((const uint4*)fh)[idx];
        ((uint4*)Bl)[idx] = ((const uint4*)fl)[idx];
    }
}

// 3-product split-bf16 mainloop: acc[16][4] covers rows {warp*16+gr, +8}, cols j*8+cc2,+1
__device__ __forceinline__ void mma_mainloop(const char* Ah, const char* Al,
                                             const unsigned int* Bh, const unsigned int* Bl,
                                             float acc[16][4], int lane, int warp) {
    int gr  = lane >> 2;
    int cc2 = (lane & 3) * 2;
    int abase = (warp * 16 + gr) * APITCH + cc2 * 2;
    #pragma unroll
    for (int ks = 0; ks < 8; ks++) {
        int ao = abase + ks * 32;
        unsigned int ah0 = *(const unsigned int*)(Ah + ao);
        unsigned int ah1 = *(const unsigned int*)(Ah + ao + 8 * APITCH);
        unsigned int ah2 = *(const unsigned int*)(Ah + ao + 16);
        unsigned int ah3 = *(const unsigned int*)(Ah + ao + 8 * APITCH + 16);
        unsigned int al0 = *(const unsigned int*)(Al + ao);
        unsigned int al1 = *(const unsigned int*)(Al + ao + 8 * APITCH);
        unsigned int al2 = *(const unsigned int*)(Al + ao + 16);
        unsigned int al3 = *(const unsigned int*)(Al + ao + 8 * APITCH + 16);
        #pragma unroll
        for (int jb = 0; jb < 4; jb++) {
            unsigned int bh[4][2], bl[4][2];
            #pragma unroll
            for (int q = 0; q < 4; q++) {
                int slot = ((ks * 16 + jb * 4 + q) * 32 + lane) * 2;
                uint2 t1 = *(const uint2*)&Bh[slot];
                uint2 t2 = *(const uint2*)&Bl[slot];
                bh[q][0] = t1.x; bh[q][1] = t1.y;
                bl[q][0] = t2.x; bl[q][1] = t2.y;
            }
            #pragma unroll
            for (int q = 0; q < 4; q++)
                mma_bf16(acc[jb * 4 + q], ah0, ah1, ah2, ah3, bh[q][0], bh[q][1]);
            #pragma unroll
            for (int q = 0; q < 4; q++)
                mma_bf16(acc[jb * 4 + q], ah0, ah1, ah2, ah3, bl[q][0], bl[q][1]);
            #pragma unroll
            for (int q = 0; q < 4; q++)
                mma_bf16(acc[jb * 4 + q], al0, al1, al2, al3, bh[q][0], bh[q][1]);
        }
    }
}

// ---------------- xf = x @ WfX + bf ----------------
#define MMA_SMEM1 (32768 * 2 + 34816 * 2 + 512)
__global__ __launch_bounds__(256, 1)
void xf_mma_kernel(const float* __restrict__ A, const float* __restrict__ bias,
                   float* __restrict__ O, int M) {
    extern __shared__ char smx[];
    unsigned int* Bh = (unsigned int*)smx;
    unsigned int* Bl = (unsigned int*)(smx + 32768);
    char* Ah = smx + 65536;
    char* Al = smx + 65536 + 34816;
    float* sbias = (float*)(smx + 65536 + 69632);
    int tid = threadIdx.x, lane = tid & 31, warp = tid >> 5;
    int row0 = blockIdx.x * 128;

    stage_B(g_bfh[1], g_bfl[1], Bh, Bl, tid);
    if (tid < 128) sbias[tid] = bias[tid];
    stage_A_split(A, row0, M, Ah, Al, tid);
    __syncthreads();

    float acc[16][4];
    #pragma unroll
    for (int j = 0; j < 16; j++)
        #pragma unroll
        for (int q = 0; q < 4; q++) acc[j][q] = 0.f;

    mma_mainloop(Ah, Al, Bh, Bl, acc, lane, warp);

    int gr  = lane >> 2;
    int cc2 = (lane & 3) * 2;
    int r1 = row0 + warp * 16 + gr;
    #pragma unroll
    for (int j = 0; j < 16; j++) {
        int col = j * 8 + cc2;
        float b0 = sbias[col], b1 = sbias[col + 1];
        if (r1 < M)
            *(float2*)&O[(size_t)r1 * 128 + col] = make_float2(acc[j][0] + b0, acc[j][1] + b1);
        if (r1 + 8 < M)
            *(float2*)&O[(size_t)(r1 + 8) * 128 + col] = make_float2(acc[j][2] + b0, acc[j][3] + b1);
    }
}

// ---------------- delta = tanh(lrelu(x@Wh1+bh1) @ Wh2 + bh2) ----------------
#define MMA_SMEM_H (32768 * 2 + 34816 * 2 + 512 + 1536)
__global__ __launch_bounds__(256, 1)
void hdelta_mma_kernel(const float* __restrict__ A, const float* __restrict__ bias,
                       const float* __restrict__ Wh2, const float* __restrict__ bh2, int M) {
    extern __shared__ char smx[];
    unsigned int* Bh = (unsigned int*)smx;
    unsigned int* Bl = (unsigned int*)(smx + 32768);
    char* Ah = smx + 65536;
    char* Al = smx + 65536 + 34816;
    float* sbias = (float*)(smx + 65536 + 69632);
    float* sW2   = (float*)(smx + 65536 + 69632 + 512);
    int tid = threadIdx.x, lane = tid & 31, warp = tid >> 5;
    int row0 = blockIdx.x * 128;

    stage_B(g_bfh[0], g_bfl[0], Bh, Bl, tid);
    if (tid < 128) sbias[tid] = bias[tid];
    if (tid >= 128 && tid < 224) *(float4*)&sW2[(tid - 128) * 4] = *(const float4*)&Wh2[(tid - 128) * 4];
    stage_A_split(A, row0, M, Ah, Al, tid);
    __syncthreads();

    float acc[16][4];
    #pragma unroll
    for (int j = 0; j < 16; j++)
        #pragma unroll
        for (int q = 0; q < 4; q++) acc[j][q] = 0.f;

    mma_mainloop(Ah, Al, Bh, Bl, acc, lane, warp);

    // epilogue: v = lrelu(acc + bias); per-row dot with Wh2 (3 cols); quad reduce; tanh
    int gr  = lane >> 2;
    int cc2 = (lane & 3) * 2;
    float pA0 = 0.f, pA1 = 0.f, pA2 = 0.f;   // row r1
    float pB0 = 0.f, pB1 = 0.f, pB2 = 0.f;   // row r1+8
    #pragma unroll
    for (int j = 0; j < 16; j++) {
        int col = j * 8 + cc2;
        float b0 = sbias[col], b1 = sbias[col + 1];
        float v0 = lrelu(acc[j][0] + b0);
        float v1 = lrelu(acc[j][1] + b1);
        float v2 = lrelu(acc[j][2] + b0);
        float v3 = lrelu(acc[j][3] + b1);
        float w00 = sW2[col * 3 + 0], w01 = sW2[col * 3 + 1], w02 = sW2[col * 3 + 2];
        float w10 = sW2[(col + 1) * 3 + 0], w11 = sW2[(col + 1) * 3 + 1], w12 = sW2[(col + 1) * 3 + 2];
        pA0 += v0 * w00 + v1 * w10;
        pA1 += v0 * w01 + v1 * w11;
        pA2 += v0 * w02 + v1 * w12;
        pB0 += v2 * w00 + v3 * w10;
        pB1 += v2 * w01 + v3 * w11;
        pB2 += v2 * w02 + v3 * w12;
    }
    // reduce across the 4 lanes of each quad (sums over all 128 columns)
    #pragma unroll
    for (int d = 1; d < 4; d <<= 1) {
        pA0 += __shfl_xor_sync(0xffffffffu, pA0, d);
        pA1 += __shfl_xor_sync(0xffffffffu, pA1, d);
        pA2 += __shfl_xor_sync(0xffffffffu, pA2, d);
        pB0 += __shfl_xor_sync(0xffffffffu, pB0, d);
        pB1 += __shfl_xor_sync(0xffffffffu, pB1, d);
        pB2 += __shfl_xor_sync(0xffffffffu, pB2, d);
    }
    if ((lane & 3) == 0) {
        int r1 = row0 + warp * 16 + gr;
        float c0 = bh2[0], c1 = bh2[1], c2 = bh2[2];
        if (r1 < M) {
            g_delta[r1 * 3 + 0] = tanhf(pA0 + c0);
            g_delta[r1 * 3 + 1] = tanhf(pA1 + c1);
            g_delta[r1 * 3 + 2] = tanhf(pA2 + c2);
        }
        if (r1 + 8 < M) {
            g_delta[(r1 + 8) * 3 + 0] = tanhf(pB0 + c0);
            g_delta[(r1 + 8) * 3 + 1] = tanhf(pB1 + c1);
            g_delta[(r1 + 8) * 3 + 2] = tanhf(pB2 + c2);
        }
    }
}

// ---------------- out = lrelu(agg@Wg1+bg1)@Wg2 + bg2 + x ----------------
#define MMA_SMEM_O (32768 * 2 + 34816 * 2 + 1024)
__global__ __launch_bounds__(256, 1)
void out_mma_kernel(const float* __restrict__ A, const float* __restrict__ b1,
                    const float* __restrict__ b2, const float* __restrict__ X,
                    float* __restrict__ O, int M) {
    extern __shared__ char smx[];
    unsigned int* Bh = (unsigned int*)smx;
    unsigned int* Bl = (unsigned int*)(smx + 32768);
    char* Ah = smx + 65536;
    char* Al = smx + 65536 + 34816;
    float* sb1 = (float*)(smx + 65536 + 69632);
    float* sb2 = (float*)(smx + 65536 + 69632 + 512);
    int tid = threadIdx.x, lane = tid & 31, warp = tid >> 5;
    int row0 = blockIdx.x * 128;
    int gr  = lane >> 2;
    int cc2 = (lane & 3) * 2;

    stage_B(g_bfh[2], g_bfl[2], Bh, Bl, tid);
    if (tid < 128) sb1[tid] = b1[tid];
    else if (tid < 256) sb2[tid - 128] = b2[tid - 128];
    stage_A_split(A, row0, M, Ah, Al, tid);
    __syncthreads();

    float acc[16][4];
    #pragma unroll
    for (int j = 0; j < 16; j++)
        #pragma unroll
        for (int q = 0; q < 4; q++) acc[j][q] = 0.f;

    mma_mainloop(Ah, Al, Bh, Bl, acc, lane, warp);
    __syncthreads();   // everyone done reading Ah/Al/Bh/Bl

    // write t = lrelu(acc + bg1) back into A tiles (split hi/lo), restage B = Wg2
    {
        int rlA = warp * 16 + gr;
        #pragma unroll
        for (int j = 0; j < 16; j++) {
            int col = j * 8 + cc2;
            float b0 = sb1[col], b1v = sb1[col + 1];
            float v0 = lrelu(acc[j][0] + b0);
            float v1 = lrelu(acc[j][1] + b1v);
            float v2 = lrelu(acc[j][2] + b0);
            float v3 = lrelu(acc[j][3] + b1v);
            unsigned int hA = pack_bf2(v0, v1);
            unsigned int hB = pack_bf2(v2, v3);
            float hf0 = __uint_as_float(hA << 16);
            float hf1 = __uint_as_float(hA & 0xFFFF0000u);
            float hf2 = __uint_as_float(hB << 16);
            float hf3 = __uint_as_float(hB & 0xFFFF0000u);
            unsigned int lA = pack_bf2(v0 - hf0, v1 - hf1);
            unsigned int lB = pack_bf2(v2 - hf2, v3 - hf3);
            *(unsigned int*)(Ah + rlA * APITCH + col * 2) = hA;
            *(unsigned int*)(Al + rlA * APITCH + col * 2) = lA;
            *(unsigned int*)(Ah + (rlA + 8) * APITCH + col * 2) = hB;
            *(unsigned int*)(Al + (rlA + 8) * APITCH + col * 2) = lB;
        }
    }
    stage_B(g_bfh[3], g_bfl[3], Bh, Bl, tid);
    __syncthreads();

    #pragma unroll
    for (int j = 0; j < 16; j++)
        #pragma unroll
        for (int q = 0; q < 4; q++) acc[j][q] = 0.f;

    mma_mainloop(Ah, Al, Bh, Bl, acc, lane, warp);

    // epilogue: + bg2 + residual x -> O
    int r1 = row0 + warp * 16 + gr;
    #pragma unroll
    for (int j = 0; j < 16; j++) {
        int col = j * 8 + cc2;
        float b0 = sb2[col], b1v = sb2[col + 1];
        if (r1 < M) {
            float2 rx = *(const float2*)&X[(size_t)r1 * 128 + col];
            *(float2*)&O[(size_t)r1 * 128 + col] =
                make_float2(acc[j][0] + b0 + rx.x, acc[j][1] + b1v + rx.y);
        }
        if (r1 + 8 < M) {
            float2 rx = *(const float2*)&X[(size_t)(r1 + 8) * 128 + col];
            *(float2*)&O[(size_t)(r1 + 8) * 128 + col] =
                make_float2(acc[j][2] + b0 + rx.x, acc[j][3] + b1v + rx.y);
        }
    }
}

// ---------------- edge aggregation: warp per dst node, unroll 4 ----------------
__global__ void agg_kernel(const float* __restrict__ pos, const float* __restrict__ Wf, int N) {
    int warp = (blockIdx.x * blockDim.x + threadIdx.x) >> 5;
    int lane = threadIdx.x & 31;
    if (warp >= N) return;
    int c = lane * 4;
    float4 w0 = *(const float4*)&Wf[c];
    float4 w1 = *(const float4*)&Wf[128 + c];
    float4 w2 = *(const float4*)&Wf[256 + c];
    float bx = g_delta[warp * 3 + 0] - pos[warp * 3 + 0];
    float by = g_delta[warp * 3 + 1] - pos[warp * 3 + 1];
    float bz = g_delta[warp * 3 + 2] - pos[warp * 3 + 2];
    int p0 = g_off[warp], p1 = g_off[warp + 1];
    float4 acc = make_float4(-INFINITY, -INFINITY, -INFINITY, -INFINITY);
    int p = p0;
    for (; p + 4 <= p1; p += 4) {
        int s0 = g_esrc[p + 0];
        int s1 = g_esrc[p + 1];
        int s2 = g_esrc[p + 2];
        int s3 = g_esrc[p + 3];
        float rx0 = pos[s0 * 3 + 0] + bx, ry0 = pos[s0 * 3 + 1] + by, rz0 = pos[s0 * 3 + 2] + bz;
        float rx1 = pos[s1 * 3 + 0] + bx, ry1 = pos[s1 * 3 + 1] + by, rz1 = pos[s1 * 3 + 2] + bz;
        float rx2 = pos[s2 * 3 + 0] + bx, ry2 = pos[s2 * 3 + 1] + by, rz2 = pos[s2 * 3 + 2] + bz;
        float rx3 = pos[s3 * 3 + 0] + bx, ry3 = pos[s3 * 3 + 1] + by, rz3 = pos[s3 * 3 + 2] + bz;
        float4 v0 = *(const float4*)&g_xf[(size_t)s0 * 128 + c];
        float4 v1 = *(const float4*)&g_xf[(size_t)s1 * 128 + c];
        float4 v2 = *(const float4*)&g_xf[(size_t)s2 * 128 + c];
        float4 v3 = *(const float4*)&g_xf[(size_t)s3 * 128 + c];
        acc.x = fmaxf(acc.x, fmaf(rz0, w2.x, fmaf(ry0, w1.x, fmaf(rx0, w0.x, v0.x))));
        acc.y = fmaxf(acc.y, fmaf(rz0, w2.y, fmaf(ry0, w1.y, fmaf(rx0, w0.y, v0.y))));
        acc.z = fmaxf(acc.z, fmaf(rz0, w2.z, fmaf(ry0, w1.z, fmaf(rx0, w0.z, v0.z))));
        acc.w = fmaxf(acc.w, fmaf(rz0, w2.w, fmaf(ry0, w1.w, fmaf(rx0, w0.w, v0.w))));
        acc.x = fmaxf(acc.x, fmaf(rz1, w2.x, fmaf(ry1, w1.x, fmaf(rx1, w0.x, v1.x))));
        acc.y = fmaxf(acc.y, fmaf(rz1, w2.y, fmaf(ry1, w1.y, fmaf(rx1, w0.y, v1.y))));
        acc.z = fmaxf(acc.z, fmaf(rz1, w2.z, fmaf(ry1, w1.z, fmaf(rx1, w0.z, v1.z))));
        acc.w = fmaxf(acc.w, fmaf(rz1, w2.w, fmaf(ry1, w1.w, fmaf(rx1, w0.w, v1.w))));
        acc.x = fmaxf(acc.x, fmaf(rz2, w2.x, fmaf(ry2, w1.x, fmaf(rx2, w0.x, v2.x))));
        acc.y = fmaxf(acc.y, fmaf(rz2, w2.y, fmaf(ry2, w1.y, fmaf(rx2, w0.y, v2.y))));
        acc.z = fmaxf(acc.z, fmaf(rz2, w2.z, fmaf(ry2, w1.z, fmaf(rx2, w0.z, v2.z))));
        acc.w = fmaxf(acc.w, fmaf(rz2, w2.w, fmaf(ry2, w1.w, fmaf(rx2, w0.w, v2.w))));
        acc.x = fmaxf(acc.x, fmaf(rz3, w2.x, fmaf(ry3, w1.x, fmaf(rx3, w0.x, v3.x))));
        acc.y = fmaxf(acc.y, fmaf(rz3, w2.y, fmaf(ry3, w1.y, fmaf(rx3, w0.y, v3.y))));
        acc.z = fmaxf(acc.z, fmaf(rz3, w2.z, fmaf(ry3, w1.z, fmaf(rx3, w0.z, v3.z))));
        acc.w = fmaxf(acc.w, fmaf(rz3, w2.w, fmaf(ry3, w1.w, fmaf(rx3, w0.w, v3.w))));
    }
    for (; p < p1; ++p) {
        int s = g_esrc[p];
        float rx = pos[s * 3 + 0] + bx, ry = pos[s * 3 + 1] + by, rz = pos[s * 3 + 2] + bz;
        float4 v = *(const float4*)&g_xf[(size_t)s * 128 + c];
        acc.x = fmaxf(acc.x, fmaf(rz, w2.x, fmaf(ry, w1.x, fmaf(rx, w0.x, v.x))));
        acc.y = fmaxf(acc.y, fmaf(rz, w2.y, fmaf(ry, w1.y, fmaf(rx, w0.y, v.y))));
        acc.z = fmaxf(acc.z, fmaf(rz, w2.z, fmaf(ry, w1.z, fmaf(rx, w0.z, v.z))));
        acc.w = fmaxf(acc.w, fmaf(rz, w2.w, fmaf(ry, w1.w, fmaf(rx, w0.w, v.w))));
    }
    float4 o;
    if (p1 > p0) {
        o.x = lrelu(acc.x); o.y = lrelu(acc.y);
        o.z = lrelu(acc.z); o.w = lrelu(acc.w);
    } else {
        o = make_float4(0.f, 0.f, 0.f, 0.f);
    }
    *(float4*)&g_agg[(size_t)warp * 128 + c] = o;
}

// ---------------- launch ----------------
extern "C" void kernel_launch(void* const* d_in, const int* in_sizes, int n_in,
                              void* d_out, int out_size) {
    const float* x   = (const float*)d_in[0];
    const float* pos = (const float*)d_in[1];
    const void*  ei  = d_in[2];
    const float* Wh1 = (const float*)d_in[3];
    const float* bh1 = (const float*)d_in[4];
    const float* Wh2 = (const float*)d_in[5];
    const float* bh2 = (const float*)d_in[6];
    const float* Wf  = (const float*)d_in[7];
    const float* bf  = (const float*)d_in[8];
    const float* Wg1 = (const float*)d_in[9];
    const float* bg1 = (const float*)d_in[10];
    const float* Wg2 = (const float*)d_in[11];
    const float* bg2 = (const float*)d_in[12];
    float* out = (float*)d_out;

    int M = in_sizes[0] / CDIM;   // 50000
    int E = in_sizes[2] / 2;      // 800000

    cudaFuncSetAttribute(xf_mma_kernel,     cudaFuncAttributeMaxDynamicSharedMemorySize, MMA_SMEM1);
    cudaFuncSetAttribute(hdelta_mma_kernel, cudaFuncAttributeMaxDynamicSharedMemorySize, MMA_SMEM_H);
    cudaFuncSetAttribute(out_mma_kernel,    cudaFuncAttributeMaxDynamicSharedMemorySize, MMA_SMEM_O);

    float *xfp, *aggp;
    cudaGetSymbolAddress((void**)&xfp,  g_xf);
    cudaGetSymbolAddress((void**)&aggp, g_agg);

    int gemm_blocks = (M + 127) / 128;
    int eblocks = (E + 255) / 256;
    int nblocks = (M + 255) / 256;
    int sblocks = (M + 1023) / 1024;
    int wblocks = (M + 7) / 8;

    static cudaStream_t s_side = nullptr;
    static cudaEvent_t  s_e0 = nullptr, s_e1 = nullptr;
    if (s_side == nullptr) {
        cudaStreamCreateWithFlags(&s_side, cudaStreamNonBlocking);
        cudaEventCreateWithFlags(&s_e0, cudaEventDisableTiming);
        cudaEventCreateWithFlags(&s_e1, cudaEventDisableTiming);
    }

    // main: weight prep (all 4 weights)
    prep_w_kernel<<<dim3(16, 4), 256>>>(Wh1, Wf + 3 * 128, Wg1, Wg2);

    // fork: CSR build on side stream
    cudaEventRecord(s_e0, 0);
    cudaStreamWaitEvent(s_side, s_e0, 0);
    detect_kernel<<<1, 32, 0, s_side>>>((const unsigned int*)ei, E);
    zero_cnt_kernel<<<nblocks, 256, 0, s_side>>>(M);
    convert_hist_kernel<<<eblocks, 256, 0, s_side>>>(ei, E);
    scanA_kernel<<<sblocks, 1024, 0, s_side>>>(M);
    scanB_kernel<<<1, 64, 0, s_side>>>(sblocks);
    scanC_kernel<<<sblocks, 1024, 0, s_side>>>(M);
    scatter_kernel<<<eblocks, 256, 0, s_side>>>(E);
    cudaEventRecord(s_e1, s_side);

    // main: node GEMMs on tensor cores
    xf_mma_kernel<<<gemm_blocks, 256, MMA_SMEM1>>>(x, bf, xfp, M);
    hdelta_mma_kernel<<<gemm_blocks, 256, MMA_SMEM_H>>>(x, bh1, Wh2, bh2, M);

    // join, then aggregate + output MLP
    cudaStreamWaitEvent(0, s_e1, 0);
    agg_kernel<<<wblocks, 256>>>(pos, Wf, M);
    out_mma_kernel<<<gemm_blocks, 256, MMA_SMEM_O>>>(aggp, bg1, bg2, x, out, M);
}